// round 6
// baseline (speedup 1.0000x reference)
#include <cuda_runtime.h>

typedef unsigned long long ull;
typedef unsigned int u32;

constexpr int cNU = 4096, cNV = 4096, cD = 256, cH = 64, cR = 5, cB = 4096;
constexpr int KSPLIT = 2;
constexpr int NPART = KSPLIT * cR;

// ---------------- device scratch ----------------
__device__ float g_row[cR * cNU];
__device__ float g_col[cR * cNV];
__device__ float g_cinv[cR * cNU];
__device__ float g_rinv[cR * cNV];
__device__ float g_uw[cR * cD * cH];
__device__ float g_vw[cR * cD * cH];
// bf16 hi/lo images (scale folded): side 0 = tv-side (for A_u), side 1 = tu-side (for A_v)
// layout: [side*5+r][k=4096][32 u32 along h]
__device__ u32 g_Bhi[2 * 5 * 131072];
__device__ u32 g_Blo[2 * 5 * 131072];
__device__ float g_pu[(size_t)NPART * cNU * cH];
__device__ float g_pv[(size_t)NPART * cNV * cH];
__device__ float g_Au[cNU * cH];
__device__ float g_Av[cNV * cH];

// ---------------- helpers ----------------
__device__ __forceinline__ u32 smem_u32(const void* p) {
    u32 a;
    asm("{ .reg .u64 t; cvta.to.shared.u64 t, %1; cvt.u32.u64 %0, t; }" : "=r"(a) : "l"(p));
    return a;
}
__device__ __forceinline__ void split2(float x0, float x1, u32 &h, u32 &l) {
    u32 hp;
    asm("cvt.rn.bf16x2.f32 %0, %1, %2;" : "=r"(hp) : "f"(x1), "f"(x0));
    float r0 = x0 - __uint_as_float(hp << 16);
    float r1 = x1 - __uint_as_float(hp & 0xFFFF0000u);
    u32 lp;
    asm("cvt.rn.bf16x2.f32 %0, %1, %2;" : "=r"(lp) : "f"(r1), "f"(r0));
    h = hp; l = lp;
}

#define LDSM4(r0, r1, r2, r3, addr) \
    asm volatile("ldmatrix.sync.aligned.m8n8.x4.shared.b16 {%0,%1,%2,%3}, [%4];" \
                 : "=r"(r0), "=r"(r1), "=r"(r2), "=r"(r3) : "r"(addr))
#define LDSM4T(r0, r1, r2, r3, addr) \
    asm volatile("ldmatrix.sync.aligned.m8n8.x4.trans.shared.b16 {%0,%1,%2,%3}, [%4];" \
                 : "=r"(r0), "=r"(r1), "=r"(r2), "=r"(r3) : "r"(addr))
#define MMA_BF16(c, a0, a1, a2, a3, b0, b1) \
    asm volatile("mma.sync.aligned.m16n8k16.row.col.f32.bf16.bf16.f32 " \
                 "{%0,%1,%2,%3}, {%4,%5,%6,%7}, {%8,%9}, {%0,%1,%2,%3};" \
                 : "+f"((c)[0]), "+f"((c)[1]), "+f"((c)[2]), "+f"((c)[3]) \
                 : "r"(a0), "r"(a1), "r"(a2), "r"(a3), "r"(b0), "r"(b1))
#define CP_ASYNC16(smaddr, gptr) \
    asm volatile("cp.async.ca.shared.global [%0], [%1], 16;" :: "r"(smaddr), "l"(gptr))
#define CP_COMMIT() asm volatile("cp.async.commit_group;" ::: "memory")
#define CP_WAIT0()  asm volatile("cp.async.wait_group 0;" ::: "memory")

// smem swizzles (byte offsets; writer and ldmatrix reader use the same formula)
__device__ __forceinline__ u32 swzA_nt(int row, int k) {   // [128][32] bf16, 64B rows
    u32 o = (u32)(row * 64 + k * 2); return o ^ ((o >> 3) & 0x30);
}
__device__ __forceinline__ u32 swzA_t(int k, int row) {    // [32][128] bf16, 256B rows
    u32 o = (u32)(k * 256 + row * 2); return o ^ ((o >> 4) & 0x70);
}
__device__ __forceinline__ u32 swzB(int k, int n) {        // [32][64] bf16, 128B rows
    u32 o = (u32)(k * 128 + n * 2); return o ^ ((o >> 3) & 0x70);
}

// ---------------- f32x2 helpers for kfeat ----------------
__device__ __forceinline__ ull dupf(float x) {
    ull r; asm("mov.b64 %0, {%1, %1};" : "=l"(r) : "f"(x)); return r;
}
__device__ __forceinline__ void ffma2(ull &d, ull a, ull b) {
    asm("fma.rn.f32x2 %0, %1, %2, %0;" : "+l"(d) : "l"(a), "l"(b));
}
union U2 { ull u; float2 f; };

// ---------------- tiny kernels ----------------
__global__ void kzero() {
    int i = blockIdx.x * blockDim.x + threadIdx.x;
    if (i < cR * cNU) { g_row[i] = 0.f; g_col[i] = 0.f; }
}

__global__ void kcumsum(const float* __restrict__ uw, const float* __restrict__ vw) {
    int i = blockIdx.x * blockDim.x + threadIdx.x;
    if (i >= cD * cH) return;
    float a = 0.f, b = 0.f;
#pragma unroll
    for (int r = 0; r < cR; r++) {
        a += uw[r * cD * cH + i]; g_uw[r * cD * cH + i] = a;
        b += vw[r * cD * cH + i]; g_vw[r * cD * cH + i] = b;
    }
}

__global__ void __launch_bounds__(256) ksums(const float* __restrict__ S) {
    constexpr int RPC = 32;
    int blk = blockIdx.x;
    int r  = blk / (cNU / RPC);
    int n0 = (blk % (cNU / RPC)) * RPC;
    const float* base = S + ((size_t)r * cNU + n0) * cNV;
    int t = threadIdx.x;
    float4 c0 = {0,0,0,0}, c1 = c0, c2 = c0, c3 = c0;
    for (int i = 0; i < RPC; i++) {
        const float4* rp = (const float4*)(base + (size_t)i * cNV);
        float4 v0 = rp[t], v1 = rp[t + 256], v2 = rp[t + 512], v3 = rp[t + 768];
        c0.x += v0.x; c0.y += v0.y; c0.z += v0.z; c0.w += v0.w;
        c1.x += v1.x; c1.y += v1.y; c1.z += v1.z; c1.w += v1.w;
        c2.x += v2.x; c2.y += v2.y; c2.z += v2.z; c2.w += v2.w;
        c3.x += v3.x; c3.y += v3.y; c3.z += v3.z; c3.w += v3.w;
        float rs = v0.x + v0.y + v0.z + v0.w + v1.x + v1.y + v1.z + v1.w
                 + v2.x + v2.y + v2.z + v2.w + v3.x + v3.y + v3.z + v3.w;
#pragma unroll
        for (int o = 16; o > 0; o >>= 1) rs += __shfl_down_sync(0xffffffffu, rs, o);
        if ((t & 31) == 0) atomicAdd(&g_row[r * cNU + n0 + i], rs);
    }
    float* col = g_col + r * cNV;
    int c = 4 * t;
    atomicAdd(&col[c+0],    c0.x); atomicAdd(&col[c+1],    c0.y);
    atomicAdd(&col[c+2],    c0.z); atomicAdd(&col[c+3],    c0.w);
    atomicAdd(&col[c+1024], c1.x); atomicAdd(&col[c+1025], c1.y);
    atomicAdd(&col[c+1026], c1.z); atomicAdd(&col[c+1027], c1.w);
    atomicAdd(&col[c+2048], c2.x); atomicAdd(&col[c+2049], c2.y);
    atomicAdd(&col[c+2050], c2.z); atomicAdd(&col[c+2051], c2.w);
    atomicAdd(&col[c+3072], c3.x); atomicAdd(&col[c+3073], c3.y);
    atomicAdd(&col[c+3074], c3.z); atomicAdd(&col[c+3075], c3.w);
}

__global__ void kinv() {
    int i = blockIdx.x * blockDim.x + threadIdx.x;
    if (i >= cR * cNU) return;
    float x = g_row[i]; g_cinv[i] = x > 0.f ? rsqrtf(x) : 0.f;
    float y = g_col[i]; g_rinv[i] = y > 0.f ? rsqrtf(y) : 0.f;
}

// ---------------- feature GEMM, epilogue writes scaled bf16 hi/lo images ----
__device__ __forceinline__ void micro_nt(const float* __restrict__ sA,
                                         const float* __restrict__ sB,
                                         int lane, int hg, ull (&acc)[4][4]) {
#pragma unroll
    for (int k4 = 0; k4 < 32; k4 += 4) {
        float4 a[4];
#pragma unroll
        for (int i = 0; i < 4; i++) a[i] = *(const float4*)(sA + (lane + 32 * i) * 36 + k4);
#pragma unroll
        for (int kk = 0; kk < 4; kk++) {
            const float* bp = sB + (k4 + kk) * 64 + hg * 8;
            longlong2 bA = *(const longlong2*)bp;
            longlong2 bB = *(const longlong2*)(bp + 4);
#pragma unroll
            for (int i = 0; i < 4; i++) {
                float av = (kk == 0) ? a[i].x : (kk == 1) ? a[i].y : (kk == 2) ? a[i].z : a[i].w;
                ull ad = dupf(av);
                ffma2(acc[i][0], ad, (ull)bA.x);
                ffma2(acc[i][1], ad, (ull)bA.y);
                ffma2(acc[i][2], ad, (ull)bB.x);
                ffma2(acc[i][3], ad, (ull)bB.y);
            }
        }
    }
}

__global__ void __launch_bounds__(256, 2) kfeat(const float* __restrict__ u_feat,
                                                const float* __restrict__ v_feat) {
    __shared__ float sA[128 * 36];
    __shared__ float sB[32 * 64];
    int sid = blockIdx.y;
    bool uside = sid < cR;
    int r = uside ? sid : sid - cR;
    const float* F  = uside ? u_feat : v_feat;
    const float* W  = (uside ? g_uw : g_vw) + r * cD * cH;
    const float* sv = (uside ? g_cinv : g_rinv) + r * 4096;
    // tu -> image side 1 (A_v operand); tv -> image side 0 (A_u operand)
    const size_t ib = (size_t)((uside ? 5 + r : r)) * 131072;
    int t = threadIdx.x, lane = t & 31, hg = t >> 5;
    int outb = blockIdx.x * 128;
    ull acc[4][4];
#pragma unroll
    for (int i = 0; i < 4; i++)
#pragma unroll
        for (int j = 0; j < 4; j++) acc[i][j] = 0ull;
    for (int kb = 0; kb < cD; kb += 32) {
#pragma unroll
        for (int q = 0; q < 2; q++) {
            int fi = t + q * 256;
            int kr = fi >> 4, c4 = (fi & 15) * 4;
            *(float4*)(sB + kr * 64 + c4) = *(const float4*)(W + (kb + kr) * 64 + c4);
        }
#pragma unroll
        for (int q = 0; q < 4; q++) {
            int fi = t + q * 256;
            int row = fi >> 3, c4 = (fi & 7) * 4;
            *(float4*)(sA + row * 36 + c4) = *(const float4*)(F + (size_t)(outb + row) * cD + kb + c4);
        }
        __syncthreads();
        micro_nt(sA, sB, lane, hg, acc);
        __syncthreads();
    }
#pragma unroll
    for (int i = 0; i < 4; i++) {
        int row = outb + lane + 32 * i;
        float s = sv[row];
        U2 w0, w1, w2, w3;
        w0.u = acc[i][0]; w1.u = acc[i][1]; w2.u = acc[i][2]; w3.u = acc[i][3];
        float f[8] = {w0.f.x, w0.f.y, w1.f.x, w1.f.y, w2.f.x, w2.f.y, w3.f.x, w3.f.y};
        size_t o = ib + (size_t)row * 32 + hg * 4;
#pragma unroll
        for (int j = 0; j < 4; j++) {
            u32 h, l;
            split2(s * f[2 * j], s * f[2 * j + 1], h, l);
            g_Bhi[o + j] = h;
            g_Blo[o + j] = l;
        }
    }
}

// ---------------- main contraction via mma.sync bf16 (3-term split) ----------
// smem buffer layout (per buf, 24 KB): Ahi @0 (8K), Alo @8192 (8K), Bhi @16384 (4K), Blo @20480 (4K)
template <bool TRANS>
__global__ void __launch_bounds__(256, 3) kmain_mma(const float* __restrict__ S) {
    __shared__ __align__(1024) unsigned char sm[2][24576];
    const int t = threadIdx.x;
    const int wid = t >> 5, lane = t & 31;
    const int tileb = blockIdx.x * 128;
    const int ks = blockIdx.y;
    const int r = blockIdx.z;
    const float* Sr = S + (size_t)r * cNU * cNV;
    const float* svec = (TRANS ? g_rinv : g_cinv) + r * 4096;
    const int sr = (TRANS ? 5 : 0) + r;
    const u32* imgh = g_Bhi + (size_t)sr * 131072;
    const u32* imgl = g_Blo + (size_t)sr * 131072;
    const int kbase = ks * 2048;
    const u32 sb = smem_u32(sm);
    constexpr int NC = 64;                              // chunks of BK=32

    const int bk_ = t >> 3, bc4 = (t & 7) * 4;          // B cp.async coords
    const u32 offB = swzB(bk_, (t & 7) * 8);

    float acc[8][4];
#pragma unroll
    for (int j = 0; j < 8; j++)
#pragma unroll
        for (int q = 0; q < 4; q++) acc[j][q] = 0.f;

    float4 ra[4];
    // A gmem loader for chunk c -> ra
    auto ldgA = [&](int c) {
        if (!TRANS) {
            const float4* ap =
                (const float4*)(Sr + (size_t)(tileb + (t >> 1)) * 4096 + kbase + c * 32 + (t & 1) * 16);
            ra[0] = ap[0]; ra[1] = ap[1]; ra[2] = ap[2]; ra[3] = ap[3];
        } else {
            const float4* ap =
                (const float4*)(Sr + (size_t)(kbase + c * 32 + (t >> 3)) * 4096 + tileb + (t & 7) * 16);
            ra[0] = ap[0]; ra[1] = ap[1]; ra[2] = ap[2]; ra[3] = ap[3];
        }
    };
    // convert ra -> split bf16, store into buf b
    auto stsA = [&](int b) {
        unsigned char* base = sm[b];
        float f[16] = {ra[0].x, ra[0].y, ra[0].z, ra[0].w, ra[1].x, ra[1].y, ra[1].z, ra[1].w,
                       ra[2].x, ra[2].y, ra[2].z, ra[2].w, ra[3].x, ra[3].y, ra[3].z, ra[3].w};
        if (!TRANS) {
            int row = t >> 1, kk = (t & 1) * 16;
#pragma unroll
            for (int j = 0; j < 8; j++) {
                u32 h, l; split2(f[2 * j], f[2 * j + 1], h, l);
                u32 off = swzA_nt(row, kk + 2 * j);
                *(u32*)(base + off) = h;
                *(u32*)(base + 8192 + off) = l;
            }
        } else {
            int k = t >> 3, rb = (t & 7) * 16;
#pragma unroll
            for (int j = 0; j < 8; j++) {
                u32 h, l; split2(f[2 * j], f[2 * j + 1], h, l);
                u32 off = swzA_t(k, rb + 2 * j);
                *(u32*)(base + off) = h;
                *(u32*)(base + 8192 + off) = l;
            }
        }
    };
    // async B copy for chunk c into buf b
    auto cpB = [&](int c, int b) {
        const u32 sbuf = sb + b * 24576;
        CP_ASYNC16(sbuf + 16384 + offB, imgh + (size_t)(kbase + c * 32 + bk_) * 32 + bc4);
        CP_ASYNC16(sbuf + 20480 + offB, imgl + (size_t)(kbase + c * 32 + bk_) * 32 + bc4);
        CP_COMMIT();
    };

    // ---- prologue ----
    ldgA(0);
    cpB(0, 0);
    stsA(0);
    ldgA(1);

    for (int c = 0; c < NC; c++) {
        CP_WAIT0();
        __syncthreads();
        if (c + 1 < NC) {
            stsA((c + 1) & 1);
            cpB(c + 1, (c + 1) & 1);
            if (c + 2 < NC) ldgA(c + 2);
        }
        const u32 sbuf = sb + (c & 1) * 24576;
        // ---- compute chunk c: 2 k-steps of 16 ----
#pragma unroll
        for (int s = 0; s < 2; s++) {
            const int k0s = s * 16;
            u32 ah0, ah1, ah2, ah3, al0, al1, al2, al3;
            if (!TRANS) {
                u32 off = swzA_nt(wid * 16 + (lane & 15), (lane >> 4) * 8 + k0s);
                LDSM4(ah0, ah1, ah2, ah3, sbuf + off);
                LDSM4(al0, al1, al2, al3, sbuf + 8192 + off);
            } else {
                int krow = k0s + (lane & 7) + ((lane >> 4) << 3);
                int col = wid * 16 + ((lane >> 3) & 1) * 8;
                u32 off = swzA_t(krow, col);
                LDSM4T(ah0, ah1, ah2, ah3, sbuf + off);
                LDSM4T(al0, al1, al2, al3, sbuf + 8192 + off);
            }
            u32 bh[4][4], bl[4][4];
            {
                int krow = k0s + (lane & 15);
#pragma unroll
                for (int g = 0; g < 4; g++) {
                    u32 off = swzB(krow, g * 16 + (lane >> 4) * 8);
                    LDSM4T(bh[g][0], bh[g][1], bh[g][2], bh[g][3], sbuf + 16384 + off);
                    LDSM4T(bl[g][0], bl[g][1], bl[g][2], bl[g][3], sbuf + 20480 + off);
                }
            }
#pragma unroll
            for (int g = 0; g < 4; g++) {
#pragma unroll
                for (int half = 0; half < 2; half++) {
                    const int j = 2 * g + half;
                    MMA_BF16(acc[j], ah0, ah1, ah2, ah3, bh[g][2 * half], bh[g][2 * half + 1]);
                    MMA_BF16(acc[j], al0, al1, al2, al3, bh[g][2 * half], bh[g][2 * half + 1]);
                    MMA_BF16(acc[j], ah0, ah1, ah2, ah3, bl[g][2 * half], bl[g][2 * half + 1]);
                }
            }
        }
    }

    // ---- epilogue: scale + store partial ----
    const int g2 = lane >> 2, t2 = lane & 3;
    const int row0 = tileb + wid * 16 + g2;
    const int row1 = row0 + 8;
    const float s0 = svec[row0], s1 = svec[row1];
    float* P = (TRANS ? g_pv : g_pu) + (size_t)(ks * cR + r) * 4096 * 64;
#pragma unroll
    for (int j = 0; j < 8; j++) {
        const int col = j * 8 + 2 * t2;
        *(float2*)(P + (size_t)row0 * 64 + col) = make_float2(s0 * acc[j][0], s0 * acc[j][1]);
        *(float2*)(P + (size_t)row1 * 64 + col) = make_float2(s1 * acc[j][2], s1 * acc[j][3]);
    }
}

__global__ void kreduce() {
    int i = blockIdx.x * blockDim.x + threadIdx.x;
    if (i >= cNU * cH) return;
    float su = 0.f, sv = 0.f;
#pragma unroll
    for (int p = 0; p < NPART; p++) {
        su += g_pu[(size_t)p * cNU * cH + i];
        sv += g_pv[(size_t)p * cNV * cH + i];
    }
    g_Au[i] = su;
    g_Av[i] = sv;
}

__global__ void kout(const int* __restrict__ u, const int* __restrict__ v,
                     const float* __restrict__ bias, float* __restrict__ out) {
    int i = blockIdx.x * blockDim.x + threadIdx.x;
    if (i >= 2 * cB * cH) return;
    int h = i & 63;
    float bv = bias[h];
    float z;
    if (i < cB * cH) {
        int b = i >> 6;
        z = g_Au[(size_t)u[b] * cH + h] + bv;
    } else {
        int b = (i - cB * cH) >> 6;
        z = g_Av[(size_t)v[b] * cH + h] + bv;
    }
    out[i] = z > 0.f ? z : 0.f;
}

// ---------------- launch ----------------
extern "C" void kernel_launch(void* const* d_in, const int* in_sizes, int n_in,
                              void* d_out, int out_size) {
    const float* u_feat   = (const float*)d_in[0];
    const float* v_feat   = (const float*)d_in[1];
    const int*   u        = (const int*)d_in[2];
    const int*   v        = (const int*)d_in[3];
    const float* support  = (const float*)d_in[4];
    const float* u_weight = (const float*)d_in[5];
    const float* v_weight = (const float*)d_in[6];
    const float* u_bias   = (const float*)d_in[7];
    float* out = (float*)d_out;

    kzero<<<80, 256>>>();
    kcumsum<<<64, 256>>>(u_weight, v_weight);
    ksums<<<640, 256>>>(support);
    kinv<<<80, 256>>>();
    kfeat<<<dim3(32, 10), 256>>>(u_feat, v_feat);
    kmain_mma<false><<<dim3(32, KSPLIT, cR), 256>>>(support);
    kmain_mma<true><<<dim3(32, KSPLIT, cR), 256>>>(support);
    kreduce<<<1024, 256>>>();
    kout<<<2048, 256>>>(u, v, u_bias, out);
}

// round 7
// speedup vs baseline: 1.3315x; 1.3315x over previous
#include <cuda_runtime.h>

typedef unsigned long long ull;
typedef unsigned int u32;

constexpr int cNU = 4096, cNV = 4096, cD = 256, cH = 64, cR = 5, cB = 4096;
constexpr int KSPLIT = 8;
constexpr int NPART = KSPLIT * cR;   // 40 partials per output matrix
constexpr int KSLICE = 4096 / KSPLIT; // 512
constexpr int NC = KSLICE / 32;       // 16 chunks per block

// ---------------- device scratch ----------------
__device__ float g_row[cR * cNU];
__device__ float g_col[cR * cNV];
__device__ float g_cinv[cR * cNU];
__device__ float g_rinv[cR * cNV];
__device__ float g_uw[cR * cD * cH];
__device__ float g_vw[cR * cD * cH];
// bf16 hi/lo images (scale folded): side 0 = tv-side (for A_u), side 1 = tu-side (for A_v)
// layout: [side*5+r][k=4096][32 u32 along h]
__device__ u32 g_Bhi[2 * 5 * 131072];
__device__ u32 g_Blo[2 * 5 * 131072];
__device__ float g_pu[(size_t)NPART * cNU * cH];
__device__ float g_pv[(size_t)NPART * cNV * cH];
__device__ float g_Au[cNU * cH];
__device__ float g_Av[cNV * cH];

// ---------------- helpers ----------------
__device__ __forceinline__ u32 smem_u32(const void* p) {
    u32 a;
    asm("{ .reg .u64 t; cvta.to.shared.u64 t, %1; cvt.u32.u64 %0, t; }" : "=r"(a) : "l"(p));
    return a;
}
__device__ __forceinline__ void split2(float x0, float x1, u32 &h, u32 &l) {
    u32 hp;
    asm("cvt.rn.bf16x2.f32 %0, %1, %2;" : "=r"(hp) : "f"(x1), "f"(x0));
    float r0 = x0 - __uint_as_float(hp << 16);
    float r1 = x1 - __uint_as_float(hp & 0xFFFF0000u);
    u32 lp;
    asm("cvt.rn.bf16x2.f32 %0, %1, %2;" : "=r"(lp) : "f"(r1), "f"(r0));
    h = hp; l = lp;
}

#define LDSM4(r0, r1, r2, r3, addr) \
    asm volatile("ldmatrix.sync.aligned.m8n8.x4.shared.b16 {%0,%1,%2,%3}, [%4];" \
                 : "=r"(r0), "=r"(r1), "=r"(r2), "=r"(r3) : "r"(addr))
#define LDSM4T(r0, r1, r2, r3, addr) \
    asm volatile("ldmatrix.sync.aligned.m8n8.x4.trans.shared.b16 {%0,%1,%2,%3}, [%4];" \
                 : "=r"(r0), "=r"(r1), "=r"(r2), "=r"(r3) : "r"(addr))
#define MMA_BF16(c, a0, a1, a2, a3, b0, b1) \
    asm volatile("mma.sync.aligned.m16n8k16.row.col.f32.bf16.bf16.f32 " \
                 "{%0,%1,%2,%3}, {%4,%5,%6,%7}, {%8,%9}, {%0,%1,%2,%3};" \
                 : "+f"((c)[0]), "+f"((c)[1]), "+f"((c)[2]), "+f"((c)[3]) \
                 : "r"(a0), "r"(a1), "r"(a2), "r"(a3), "r"(b0), "r"(b1))
#define CP_ASYNC16(smaddr, gptr) \
    asm volatile("cp.async.ca.shared.global [%0], [%1], 16;" :: "r"(smaddr), "l"(gptr))
#define CP_COMMIT() asm volatile("cp.async.commit_group;" ::: "memory")
#define CP_WAIT0()  asm volatile("cp.async.wait_group 0;" ::: "memory")

// smem swizzles (byte offsets; writer and ldmatrix reader use the same formula)
__device__ __forceinline__ u32 swzA_nt(int row, int k) {   // [128][32] bf16, 64B rows
    u32 o = (u32)(row * 64 + k * 2); return o ^ ((o >> 3) & 0x30);
}
__device__ __forceinline__ u32 swzA_t(int k, int row) {    // [32][128] bf16, 256B rows
    u32 o = (u32)(k * 256 + row * 2); return o ^ ((o >> 4) & 0x70);
}
__device__ __forceinline__ u32 swzB(int k, int n) {        // [32][64] bf16, 128B rows
    u32 o = (u32)(k * 128 + n * 2); return o ^ ((o >> 3) & 0x70);
}

// ---------------- f32x2 helpers for kfeat ----------------
__device__ __forceinline__ ull dupf(float x) {
    ull r; asm("mov.b64 %0, {%1, %1};" : "=l"(r) : "f"(x)); return r;
}
__device__ __forceinline__ void ffma2(ull &d, ull a, ull b) {
    asm("fma.rn.f32x2 %0, %1, %2, %0;" : "+l"(d) : "l"(a), "l"(b));
}
union U2 { ull u; float2 f; };

// ---------------- tiny kernels ----------------
__global__ void kzero() {
    int i = blockIdx.x * blockDim.x + threadIdx.x;
    if (i < cR * cNU) { g_row[i] = 0.f; g_col[i] = 0.f; }
}

__global__ void kcumsum(const float* __restrict__ uw, const float* __restrict__ vw) {
    int i = blockIdx.x * blockDim.x + threadIdx.x;
    if (i >= cD * cH) return;
    float a = 0.f, b = 0.f;
#pragma unroll
    for (int r = 0; r < cR; r++) {
        a += uw[r * cD * cH + i]; g_uw[r * cD * cH + i] = a;
        b += vw[r * cD * cH + i]; g_vw[r * cD * cH + i] = b;
    }
}

__global__ void __launch_bounds__(256) ksums(const float* __restrict__ S) {
    constexpr int RPC = 32;
    int blk = blockIdx.x;
    int r  = blk / (cNU / RPC);
    int n0 = (blk % (cNU / RPC)) * RPC;
    const float* base = S + ((size_t)r * cNU + n0) * cNV;
    int t = threadIdx.x;
    float4 c0 = {0,0,0,0}, c1 = c0, c2 = c0, c3 = c0;
    for (int i = 0; i < RPC; i++) {
        const float4* rp = (const float4*)(base + (size_t)i * cNV);
        float4 v0 = rp[t], v1 = rp[t + 256], v2 = rp[t + 512], v3 = rp[t + 768];
        c0.x += v0.x; c0.y += v0.y; c0.z += v0.z; c0.w += v0.w;
        c1.x += v1.x; c1.y += v1.y; c1.z += v1.z; c1.w += v1.w;
        c2.x += v2.x; c2.y += v2.y; c2.z += v2.z; c2.w += v2.w;
        c3.x += v3.x; c3.y += v3.y; c3.z += v3.z; c3.w += v3.w;
        float rs = v0.x + v0.y + v0.z + v0.w + v1.x + v1.y + v1.z + v1.w
                 + v2.x + v2.y + v2.z + v2.w + v3.x + v3.y + v3.z + v3.w;
#pragma unroll
        for (int o = 16; o > 0; o >>= 1) rs += __shfl_down_sync(0xffffffffu, rs, o);
        if ((t & 31) == 0) atomicAdd(&g_row[r * cNU + n0 + i], rs);
    }
    float* col = g_col + r * cNV;
    int c = 4 * t;
    atomicAdd(&col[c+0],    c0.x); atomicAdd(&col[c+1],    c0.y);
    atomicAdd(&col[c+2],    c0.z); atomicAdd(&col[c+3],    c0.w);
    atomicAdd(&col[c+1024], c1.x); atomicAdd(&col[c+1025], c1.y);
    atomicAdd(&col[c+1026], c1.z); atomicAdd(&col[c+1027], c1.w);
    atomicAdd(&col[c+2048], c2.x); atomicAdd(&col[c+2049], c2.y);
    atomicAdd(&col[c+2050], c2.z); atomicAdd(&col[c+2051], c2.w);
    atomicAdd(&col[c+3072], c3.x); atomicAdd(&col[c+3073], c3.y);
    atomicAdd(&col[c+3074], c3.z); atomicAdd(&col[c+3075], c3.w);
}

__global__ void kinv() {
    int i = blockIdx.x * blockDim.x + threadIdx.x;
    if (i >= cR * cNU) return;
    float x = g_row[i]; g_cinv[i] = x > 0.f ? rsqrtf(x) : 0.f;
    float y = g_col[i]; g_rinv[i] = y > 0.f ? rsqrtf(y) : 0.f;
}

// ---------------- feature GEMM, epilogue writes scaled bf16 hi/lo images ----
__device__ __forceinline__ void micro_nt(const float* __restrict__ sA,
                                         const float* __restrict__ sB,
                                         int lane, int hg, ull (&acc)[4][4]) {
#pragma unroll
    for (int k4 = 0; k4 < 32; k4 += 4) {
        float4 a[4];
#pragma unroll
        for (int i = 0; i < 4; i++) a[i] = *(const float4*)(sA + (lane + 32 * i) * 36 + k4);
#pragma unroll
        for (int kk = 0; kk < 4; kk++) {
            const float* bp = sB + (k4 + kk) * 64 + hg * 8;
            longlong2 bA = *(const longlong2*)bp;
            longlong2 bB = *(const longlong2*)(bp + 4);
#pragma unroll
            for (int i = 0; i < 4; i++) {
                float av = (kk == 0) ? a[i].x : (kk == 1) ? a[i].y : (kk == 2) ? a[i].z : a[i].w;
                ull ad = dupf(av);
                ffma2(acc[i][0], ad, (ull)bA.x);
                ffma2(acc[i][1], ad, (ull)bA.y);
                ffma2(acc[i][2], ad, (ull)bB.x);
                ffma2(acc[i][3], ad, (ull)bB.y);
            }
        }
    }
}

__global__ void __launch_bounds__(256, 2) kfeat(const float* __restrict__ u_feat,
                                                const float* __restrict__ v_feat) {
    __shared__ float sA[128 * 36];
    __shared__ float sB[32 * 64];
    int sid = blockIdx.y;
    bool uside = sid < cR;
    int r = uside ? sid : sid - cR;
    const float* F  = uside ? u_feat : v_feat;
    const float* W  = (uside ? g_uw : g_vw) + r * cD * cH;
    const float* sv = (uside ? g_cinv : g_rinv) + r * 4096;
    // tu -> image side 1 (A_v operand); tv -> image side 0 (A_u operand)
    const size_t ib = (size_t)((uside ? 5 + r : r)) * 131072;
    int t = threadIdx.x, lane = t & 31, hg = t >> 5;
    int outb = blockIdx.x * 128;
    ull acc[4][4];
#pragma unroll
    for (int i = 0; i < 4; i++)
#pragma unroll
        for (int j = 0; j < 4; j++) acc[i][j] = 0ull;
    for (int kb = 0; kb < cD; kb += 32) {
#pragma unroll
        for (int q = 0; q < 2; q++) {
            int fi = t + q * 256;
            int kr = fi >> 4, c4 = (fi & 15) * 4;
            *(float4*)(sB + kr * 64 + c4) = *(const float4*)(W + (kb + kr) * 64 + c4);
        }
#pragma unroll
        for (int q = 0; q < 4; q++) {
            int fi = t + q * 256;
            int row = fi >> 3, c4 = (fi & 7) * 4;
            *(float4*)(sA + row * 36 + c4) = *(const float4*)(F + (size_t)(outb + row) * cD + kb + c4);
        }
        __syncthreads();
        micro_nt(sA, sB, lane, hg, acc);
        __syncthreads();
    }
#pragma unroll
    for (int i = 0; i < 4; i++) {
        int row = outb + lane + 32 * i;
        float s = sv[row];
        U2 w0, w1, w2, w3;
        w0.u = acc[i][0]; w1.u = acc[i][1]; w2.u = acc[i][2]; w3.u = acc[i][3];
        float f[8] = {w0.f.x, w0.f.y, w1.f.x, w1.f.y, w2.f.x, w2.f.y, w3.f.x, w3.f.y};
        size_t o = ib + (size_t)row * 32 + hg * 4;
#pragma unroll
        for (int j = 0; j < 4; j++) {
            u32 h, l;
            split2(s * f[2 * j], s * f[2 * j + 1], h, l);
            g_Bhi[o + j] = h;
            g_Blo[o + j] = l;
        }
    }
}

// ---------------- main contraction via mma.sync bf16 (3-term split) ----------
// smem per buf (24 KB): Ahi @0 (8K), Alo @8192 (8K), Bhi @16384 (4K), Blo @20480 (4K)
template <bool TRANS>
__device__ __forceinline__ void kmain_body(const float* __restrict__ S,
                                           unsigned char (*sm)[24576],
                                           int r, int tileb, int ks) {
    const int t = threadIdx.x;
    const int wid = t >> 5, lane = t & 31;
    const float* Sr = S + (size_t)r * cNU * cNV;
    const float* svec = (TRANS ? g_rinv : g_cinv) + r * 4096;
    const int sr = (TRANS ? 5 : 0) + r;
    const u32* imgh = g_Bhi + (size_t)sr * 131072;
    const u32* imgl = g_Blo + (size_t)sr * 131072;
    const int kbase = ks * KSLICE;
    const u32 sb = smem_u32(sm);

    const int bk_ = t >> 3, bc4 = (t & 7) * 4;
    const u32 offB = swzB(bk_, (t & 7) * 8);

    float acc[8][4];
#pragma unroll
    for (int j = 0; j < 8; j++)
#pragma unroll
        for (int q = 0; q < 4; q++) acc[j][q] = 0.f;

    float4 ra[4];
    auto ldgA = [&](int c) {
        if (!TRANS) {
            const float4* ap =
                (const float4*)(Sr + (size_t)(tileb + (t >> 1)) * 4096 + kbase + c * 32 + (t & 1) * 16);
            ra[0] = ap[0]; ra[1] = ap[1]; ra[2] = ap[2]; ra[3] = ap[3];
        } else {
            const float4* ap =
                (const float4*)(Sr + (size_t)(kbase + c * 32 + (t >> 3)) * 4096 + tileb + (t & 7) * 16);
            ra[0] = ap[0]; ra[1] = ap[1]; ra[2] = ap[2]; ra[3] = ap[3];
        }
    };
    auto stsA = [&](int b) {
        unsigned char* base = sm[b];
        float f[16] = {ra[0].x, ra[0].y, ra[0].z, ra[0].w, ra[1].x, ra[1].y, ra[1].z, ra[1].w,
                       ra[2].x, ra[2].y, ra[2].z, ra[2].w, ra[3].x, ra[3].y, ra[3].z, ra[3].w};
        if (!TRANS) {
            int row = t >> 1, kk = (t & 1) * 16;
#pragma unroll
            for (int j = 0; j < 8; j++) {
                u32 h, l; split2(f[2 * j], f[2 * j + 1], h, l);
                u32 off = swzA_nt(row, kk + 2 * j);
                *(u32*)(base + off) = h;
                *(u32*)(base + 8192 + off) = l;
            }
        } else {
            int k = t >> 3, rb = (t & 7) * 16;
#pragma unroll
            for (int j = 0; j < 8; j++) {
                u32 h, l; split2(f[2 * j], f[2 * j + 1], h, l);
                u32 off = swzA_t(k, rb + 2 * j);
                *(u32*)(base + off) = h;
                *(u32*)(base + 8192 + off) = l;
            }
        }
    };
    auto cpB = [&](int c, int b) {
        const u32 sbuf = sb + b * 24576;
        CP_ASYNC16(sbuf + 16384 + offB, imgh + (size_t)(kbase + c * 32 + bk_) * 32 + bc4);
        CP_ASYNC16(sbuf + 20480 + offB, imgl + (size_t)(kbase + c * 32 + bk_) * 32 + bc4);
        CP_COMMIT();
    };

    // ---- prologue ----
    ldgA(0);
    cpB(0, 0);
    stsA(0);
    ldgA(1);

    for (int c = 0; c < NC; c++) {
        CP_WAIT0();
        __syncthreads();
        if (c + 1 < NC) {
            stsA((c + 1) & 1);
            cpB(c + 1, (c + 1) & 1);
            if (c + 2 < NC) ldgA(c + 2);
        }
        const u32 sbuf = sb + (c & 1) * 24576;
#pragma unroll
        for (int s = 0; s < 2; s++) {
            const int k0s = s * 16;
            u32 ah0, ah1, ah2, ah3, al0, al1, al2, al3;
            if (!TRANS) {
                u32 off = swzA_nt(wid * 16 + (lane & 15), (lane >> 4) * 8 + k0s);
                LDSM4(ah0, ah1, ah2, ah3, sbuf + off);
                LDSM4(al0, al1, al2, al3, sbuf + 8192 + off);
            } else {
                int krow = k0s + (lane & 7) + ((lane >> 4) << 3);
                int col = wid * 16 + ((lane >> 3) & 1) * 8;
                u32 off = swzA_t(krow, col);
                LDSM4T(ah0, ah1, ah2, ah3, sbuf + off);
                LDSM4T(al0, al1, al2, al3, sbuf + 8192 + off);
            }
            u32 bh[4][4], bl[4][4];
            {
                int krow = k0s + (lane & 15);
#pragma unroll
                for (int g = 0; g < 4; g++) {
                    u32 off = swzB(krow, g * 16 + (lane >> 4) * 8);
                    LDSM4T(bh[g][0], bh[g][1], bh[g][2], bh[g][3], sbuf + 16384 + off);
                    LDSM4T(bl[g][0], bl[g][1], bl[g][2], bl[g][3], sbuf + 20480 + off);
                }
            }
#pragma unroll
            for (int g = 0; g < 4; g++) {
#pragma unroll
                for (int half = 0; half < 2; half++) {
                    const int j = 2 * g + half;
                    MMA_BF16(acc[j], ah0, ah1, ah2, ah3, bh[g][2 * half], bh[g][2 * half + 1]);
                    MMA_BF16(acc[j], al0, al1, al2, al3, bh[g][2 * half], bh[g][2 * half + 1]);
                    MMA_BF16(acc[j], ah0, ah1, ah2, ah3, bl[g][2 * half], bl[g][2 * half + 1]);
                }
            }
        }
    }

    const int g2 = lane >> 2, t2 = lane & 3;
    const int row0 = tileb + wid * 16 + g2;
    const int row1 = row0 + 8;
    const float s0 = svec[row0], s1 = svec[row1];
    float* P = (TRANS ? g_pv : g_pu) + (size_t)(ks * cR + r) * 4096 * 64;
#pragma unroll
    for (int j = 0; j < 8; j++) {
        const int col = j * 8 + 2 * t2;
        *(float2*)(P + (size_t)row0 * 64 + col) = make_float2(s0 * acc[j][0], s0 * acc[j][1]);
        *(float2*)(P + (size_t)row1 * 64 + col) = make_float2(s1 * acc[j][2], s1 * acc[j][3]);
    }
}

__global__ void __launch_bounds__(256, 2) kmain_all(const float* __restrict__ S) {
    __shared__ __align__(1024) unsigned char sm[2][24576];
    const int z = blockIdx.z;
    const int side = z / cR, r = z % cR;
    const int tileb = blockIdx.x * 128;
    const int ks = blockIdx.y;
    if (side == 0) kmain_body<false>(S, sm, r, tileb, ks);
    else           kmain_body<true >(S, sm, r, tileb, ks);
}

__global__ void kreduce() {
    int i = blockIdx.x * blockDim.x + threadIdx.x;
    if (i >= cNU * cH) return;
    float su = 0.f, sv = 0.f;
#pragma unroll 8
    for (int p = 0; p < NPART; p++) {
        su += g_pu[(size_t)p * cNU * cH + i];
        sv += g_pv[(size_t)p * cNV * cH + i];
    }
    g_Au[i] = su;
    g_Av[i] = sv;
}

__global__ void kout(const int* __restrict__ u, const int* __restrict__ v,
                     const float* __restrict__ bias, float* __restrict__ out) {
    int i = blockIdx.x * blockDim.x + threadIdx.x;
    if (i >= 2 * cB * cH) return;
    int h = i & 63;
    float bv = bias[h];
    float z;
    if (i < cB * cH) {
        int b = i >> 6;
        z = g_Au[(size_t)u[b] * cH + h] + bv;
    } else {
        int b = (i - cB * cH) >> 6;
        z = g_Av[(size_t)v[b] * cH + h] + bv;
    }
    out[i] = z > 0.f ? z : 0.f;
}

// ---------------- launch ----------------
extern "C" void kernel_launch(void* const* d_in, const int* in_sizes, int n_in,
                              void* d_out, int out_size) {
    const float* u_feat   = (const float*)d_in[0];
    const float* v_feat   = (const float*)d_in[1];
    const int*   u        = (const int*)d_in[2];
    const int*   v        = (const int*)d_in[3];
    const float* support  = (const float*)d_in[4];
    const float* u_weight = (const float*)d_in[5];
    const float* v_weight = (const float*)d_in[6];
    const float* u_bias   = (const float*)d_in[7];
    float* out = (float*)d_out;

    kzero<<<80, 256>>>();
    kcumsum<<<64, 256>>>(u_weight, v_weight);
    ksums<<<640, 256>>>(support);
    kinv<<<80, 256>>>();
    kfeat<<<dim3(32, 10), 256>>>(u_feat, v_feat);
    kmain_all<<<dim3(32, KSPLIT, 2 * cR), 256>>>(support);
    kreduce<<<1024, 256>>>();
    kout<<<2048, 256>>>(u, v, u_bias, out);
}